// round 8
// baseline (speedup 1.0000x reference)
#include <cuda_runtime.h>
#include <cstdint>
#include <math.h>

#define Tt 64
#define NT 512
#define EPSF 1e-8f

__device__ __forceinline__ float sigmoidf_(float x) { return 1.f / (1.f + __expf(-x)); }
__device__ __forceinline__ float softplusf_(float x) { return (x > 20.f) ? x : log1pf(expf(x)); }

__device__ __forceinline__ uint32_t s2u(const void* p) {
    uint32_t a;
    asm("{ .reg .u64 t; cvta.to.shared.u64 t, %1; cvt.u32.u64 %0, t; }" : "=r"(a) : "l"(p));
    return a;
}
__device__ __forceinline__ void st_peer(const void* lp, uint32_t peer, float v) {
    uint32_t la = s2u(lp), ra;
    asm("mapa.shared::cluster.u32 %0, %1, %2;" : "=r"(ra) : "r"(la), "r"(peer));
    asm volatile("st.shared::cluster.f32 [%0], %1;" :: "r"(ra), "f"(v));
}
#define CARRIVE() asm volatile("barrier.cluster.arrive.aligned;" ::: "memory")
#define CWAIT()   asm volatile("barrier.cluster.wait.aligned;" ::: "memory")
#define CSYNC() do { CARRIVE(); CWAIT(); } while (0)

struct __align__(16) Smem {
    float Whs[128 * 272];     // head weights: our K-half x all 272 outs
    float Wcs[128 * 128];     // controller: full cat-K x our 128 cols
    float scratchU[2176];     // [0..1023] raw p/w arrays; [1024..2047] butterfly; GEMV partials
    float scratchF[768];
    float chalf[128];
    float rv[64];
    float cat[128];
    float hl[272], hp[272];
    float fcl[64], fcp[2][64];
    float kw[64], kr[64], ev[64], av[64];
    float redA[32], redB[32];
    float red2[8], sc[16];
    float haloWp[2], haloWv[2], haloRp[2], haloRv[2];
    float rpart[64];
    float bws[200], brs[72], bfs[64], bcc[128];
};

__global__ __launch_bounds__(NT, 1) __cluster_dims__(2, 1, 1)
void ntm_kernel(const float* __restrict__ x,
                const float* __restrict__ Wc, const float* __restrict__ bc,
                const float* __restrict__ Wr, const float* __restrict__ br,
                const float* __restrict__ Ww, const float* __restrict__ bw,
                const float* __restrict__ Wf, const float* __restrict__ bf,
                const float* __restrict__ r_bias, const float* __restrict__ w_bias,
                const float* __restrict__ M_bias, float* __restrict__ out) {
    extern __shared__ float smem_raw[];
    Smem& s = *reinterpret_cast<Smem*>(smem_raw);
    const int tid = threadIdx.x;
    const int lane = tid & 31, wid = tid >> 5;
    uint32_t rank;
    asm("mov.u32 %0, %%cluster_ctarank;" : "=r"(rank));
    const uint32_t peer = rank ^ 1u;
    const int b = blockIdx.x >> 1;
    const float4* Wf4  = (const float4*)Wf;
    const float4* Wcs4 = (const float4*)s.Wcs;
    const float4* Whs4 = (const float4*)s.Whs;

    float Mreg[64];
    float q, d;

    // ---- init ----
    for (int i = tid; i < 128 * 128; i += NT) {
        int j = i >> 7, c = i & 127;
        s.Wcs[i] = Wc[(size_t)j * 256 + rank * 128 + c];
    }
    for (int i = tid; i < 128 * 272; i += NT) {
        int j = i / 272, col = i - j * 272;
        int gk = rank * 128 + j;
        float v = 0.f;
        if (col < 198) v = Ww[(size_t)gk * 198 + col];
        else if (col < 268) v = Wr[(size_t)gk * 70 + (col - 198)];
        s.Whs[i] = v;
    }
    {
        const int row = rank * 512 + tid;
        q = 0.f;
        const float* Mb = M_bias + (size_t)row * 64;
        #pragma unroll
        for (int j = 0; j < 64; ++j) { float v = Mb[j]; Mreg[j] = v; q += v * v; }
    }
    float wr = w_bias[rank * 512 + tid];
    if (tid < 64)  s.rv[tid] = r_bias[tid];
    if (tid < 198) s.bws[tid] = bw[tid];
    if (tid < 70)  s.brs[tid] = br[tid];
    if (tid < 64)  s.bfs[tid] = bf[tid];
    if (tid < 128) s.bcc[tid] = bc[rank * 128 + tid];
    float xreg = (tid < 64) ? x[(size_t)b * Tt * 64 + tid] : 0.f;
    __syncthreads();
    CSYNC();

    for (int t = 0; t < Tt; ++t) {
        const int par = t & 1;
        if (tid < 64) s.cat[tid] = xreg;
        else if (tid < 128) s.cat[tid] = s.rv[tid - 64];
        __syncthreads();                                // S1
        if (tid < 64 && t + 1 < Tt)
            xreg = x[((size_t)b * Tt + t + 1) * 64 + tid];

        // ---- controller GEMV ----
        {
            const int g = tid & 31, sp = tid >> 5;
            float4 acc = make_float4(0.f, 0.f, 0.f, 0.f);
            #pragma unroll
            for (int j = 0; j < 8; ++j) {
                float v = s.cat[sp * 8 + j];
                float4 w4 = Wcs4[(size_t)(sp * 8 + j) * 32 + g];
                acc.x = fmaf(v, w4.x, acc.x); acc.y = fmaf(v, w4.y, acc.y);
                acc.z = fmaf(v, w4.z, acc.z); acc.w = fmaf(v, w4.w, acc.w);
            }
            *(float4*)(s.scratchU + sp * 128 + 4 * g) = acc;
        }
        __syncthreads();                                // S2
        if (tid < 128) {
            float acc = s.bcc[tid];
            #pragma unroll
            for (int k = 0; k < 16; ++k) acc += s.scratchU[k * 128 + tid];
            s.chalf[tid] = tanhf(acc);
        }
        __syncthreads();                                // S3

        // ---- head GEMV partials + FC c-part ----
        {
            int g = tid % 68, sp = tid / 68;
            float4 acc = make_float4(0.f, 0.f, 0.f, 0.f);
            #pragma unroll
            for (int j = 0; j < 16; ++j) {
                float v = s.chalf[sp * 16 + j];
                float4 w4 = Whs4[(size_t)(sp * 16 + j) * 68 + g];
                acc.x = fmaf(v, w4.x, acc.x); acc.y = fmaf(v, w4.y, acc.y);
                acc.z = fmaf(v, w4.z, acc.z); acc.w = fmaf(v, w4.w, acc.w);
            }
            *(float4*)(s.scratchU + sp * 272 + 4 * g) = acc;
            if (tid < 32) {
                int g2 = 36 + tid;
                float4 a2 = make_float4(0.f, 0.f, 0.f, 0.f);
                #pragma unroll
                for (int j = 0; j < 16; ++j) {
                    float v = s.chalf[7 * 16 + j];
                    float4 w4 = Whs4[(size_t)(7 * 16 + j) * 68 + g2];
                    a2.x = fmaf(v, w4.x, a2.x); a2.y = fmaf(v, w4.y, a2.y);
                    a2.z = fmaf(v, w4.z, a2.z); a2.w = fmaf(v, w4.w, a2.w);
                }
                *(float4*)(s.scratchU + 7 * 272 + 4 * g2) = a2;
            }
            if (tid >= 384) {
                int ft = tid - 384;
                int gf = ft & 15, spf = ft >> 4;
                float4 af = make_float4(0.f, 0.f, 0.f, 0.f);
                #pragma unroll
                for (int j = 0; j < 16; ++j) {
                    float v = s.chalf[spf * 16 + j];
                    float4 w4 = Wf4[(size_t)(rank * 128 + spf * 16 + j) * 16 + gf];
                    af.x = fmaf(v, w4.x, af.x); af.y = fmaf(v, w4.y, af.y);
                    af.z = fmaf(v, w4.z, af.z); af.w = fmaf(v, w4.w, af.w);
                }
                *(float4*)(s.scratchF + spf * 64 + 4 * gf) = af;
            }
        }
        __syncthreads();                                // S4
        if (tid < 272) {
            float acc = 0.f;
            #pragma unroll
            for (int k = 0; k < 8; ++k) acc += s.scratchU[k * 272 + tid];
            s.hl[tid] = acc;
            st_peer(&s.hp[tid], peer, acc);
        } else if (tid < 336) {
            int ft = tid - 272;
            float acc = 0.f;
            #pragma unroll
            for (int k = 0; k < 8; ++k) acc += s.scratchF[k * 64 + ft];
            s.fcl[ft] = acc;
            st_peer(&s.fcp[par][ft], peer, acc);
        }
        CSYNC();                                        // C1

        // ---- transforms ----
        {
            float hv = 0.f;
            if (tid < 268)
                hv = s.hl[tid] + s.hp[tid] + ((tid < 198) ? s.bws[tid] : s.brs[tid - 198]);
            float kv = 0.f;
            if (tid < 64 || (tid >= 198 && tid < 262)) kv = tanhf(hv);
            if (tid < 64) s.kw[tid] = kv;
            else if (tid < 70) {
                const unsigned m6 = 0x3Fu;
                float a0 = __shfl_sync(m6, hv, 2);
                float a1 = __shfl_sync(m6, hv, 3);
                float a2 = __shfl_sync(m6, hv, 4);
                if (lane == 0) s.sc[0] = softplusf_(hv);
                else if (lane == 1) s.sc[1] = sigmoidf_(hv);
                else if (lane == 5) s.sc[5] = 1.f + softplusf_(hv);
                else {
                    float m = fmaxf(a0, fmaxf(a1, a2));
                    float e0 = __expf(a0 - m), e1 = __expf(a1 - m), e2 = __expf(a2 - m);
                    float z = e0 + e1 + e2;
                    float mine = (lane == 2) ? e0 : (lane == 3) ? e1 : e2;
                    s.sc[2 + (lane - 2)] = mine / z;
                }
            }
            else if (tid < 134) s.ev[tid - 70] = sigmoidf_(hv);
            else if (tid < 198) s.av[tid - 134] = tanhf(hv);
            else if (tid < 262) s.kr[tid - 198] = kv;
            else if (tid < 268) {
                const unsigned m6 = 0xFC0u;
                float a0 = __shfl_sync(m6, hv, 8);
                float a1 = __shfl_sync(m6, hv, 9);
                float a2 = __shfl_sync(m6, hv, 10);
                if (lane == 6) s.sc[8] = softplusf_(hv);
                else if (lane == 7) s.sc[9] = sigmoidf_(hv);
                else if (lane == 11) s.sc[13] = 1.f + softplusf_(hv);
                else {
                    float m = fmaxf(a0, fmaxf(a1, a2));
                    float e0 = __expf(a0 - m), e1 = __expf(a1 - m), e2 = __expf(a2 - m);
                    float z = e0 + e1 + e2;
                    float mine = (lane == 8) ? e0 : (lane == 9) ? e1 : e2;
                    s.sc[10 + (lane - 8)] = mine / z;
                }
            }
            float qq = kv * kv;
            if (wid < 2 || (wid >= 6 && wid <= 8)) {
                #pragma unroll
                for (int o = 16; o; o >>= 1) qq += __shfl_xor_sync(0xffffffffu, qq, o);
                if (lane == 0) s.red2[wid < 2 ? wid : wid - 4] = qq;
            }
        }
        __syncthreads();                                // S5

        // ---- Pass A: d = dot(Mreg, kw) ----
        d = 0.f;
        #pragma unroll
        for (int j4 = 0; j4 < 16; ++j4) {
            float4 kk = *(const float4*)(s.kw + 4 * j4);
            d += Mreg[4*j4]*kk.x + Mreg[4*j4+1]*kk.y + Mreg[4*j4+2]*kk.z + Mreg[4*j4+3]*kk.w;
        }

        // ---- write-head addressing (barriers hidden) ----
        float w;
        {
            float knw = sqrtf(s.red2[0] + s.red2[1]);
            float beta = s.sc[0], gg = s.sc[1];
            float sh0 = s.sc[2], sh1 = s.sc[3], sh2 = s.sc[4], gamma = s.sc[5];
            float p = __expf(beta * d / (sqrtf(q) * knw + EPSF));
            s.scratchU[tid] = p;
            s.scratchU[512 + tid] = wr;
            float pw = p;
            #pragma unroll
            for (int o = 16; o; o >>= 1) pw += __shfl_xor_sync(0xffffffffu, pw, o);
            if (lane == 0) { s.redA[wid] = pw; st_peer(&s.redA[16 + wid], peer, pw); }
            if (tid == 511) { st_peer(&s.haloWp[0], peer, p); st_peer(&s.haloWv[0], peer, wr); }
            if (tid == 0)   { st_peer(&s.haloWp[1], peer, p); st_peer(&s.haloWv[1], peer, wr); }
            __syncthreads();                            // order raw arrays + local partials
            CARRIVE();                                  // C2 arrive
            float pl = tid ? s.scratchU[tid - 1] : 0.f;
            float pr = (tid < 511) ? s.scratchU[tid + 1] : 0.f;
            float vl = tid ? s.scratchU[512 + tid - 1] : 0.f;
            float vr = (tid < 511) ? s.scratchU[512 + tid + 1] : 0.f;
            CWAIT();                                    // C2 wait
            if (tid == 0)   { pl = s.haloWp[0]; vl = s.haloWv[0]; }
            if (tid == 511) { pr = s.haloWp[1]; vr = s.haloWv[1]; }
            float Z = 0.f;
            #pragma unroll
            for (int k = 0; k < 8; ++k) {
                float4 v4 = ((const float4*)s.redA)[k];
                Z += (v4.x + v4.y) + (v4.z + v4.w);
            }
            float invZ = 1.f / Z;
            float ps = sh0 * pr + sh1 * p  + sh2 * pl;
            float vs = sh0 * vr + sh1 * wr + sh2 * vl;
            float ws = gg * invZ * ps + (1.f - gg) * vs;
            float wp = exp2f(gamma * __log2f(ws + EPSF));
            float sw = wp;
            #pragma unroll
            for (int o = 16; o; o >>= 1) sw += __shfl_xor_sync(0xffffffffu, sw, o);
            if (lane == 0) { s.redB[wid] = sw; st_peer(&s.redB[16 + wid], peer, sw); }
            CARRIVE();                                  // C3 arrive

            // hidden: Pass-B scalars (independent of w): u = a - M*e
            float dM = 0.f, dU = 0.f, mm = 0.f, qU = 0.f;
            #pragma unroll
            for (int j4 = 0; j4 < 16; ++j4) {
                float4 kk = *(const float4*)(s.kr + 4 * j4);
                float4 ee = *(const float4*)(s.ev + 4 * j4);
                float4 aa = *(const float4*)(s.av + 4 * j4);
                #pragma unroll
                for (int e = 0; e < 4; ++e) {
                    int j = 4 * j4 + e;
                    float ev_ = (e==0)?ee.x:(e==1)?ee.y:(e==2)?ee.z:ee.w;
                    float av_ = (e==0)?aa.x:(e==1)?aa.y:(e==2)?aa.z:aa.w;
                    float kv_ = (e==0)?kk.x:(e==1)?kk.y:(e==2)?kk.z:kk.w;
                    float mr = Mreg[j];
                    float u = fmaf(-mr, ev_, av_);
                    dM = fmaf(mr, kv_, dM);
                    dU = fmaf(u,  kv_, dU);
                    mm = fmaf(mr, u,  mm);
                    qU = fmaf(u,  u,  qU);
                }
            }
            CWAIT();                                    // C3 wait (hidden by loop above)
            float S = 0.f;
            #pragma unroll
            for (int k = 0; k < 8; ++k) {
                float4 v4 = ((const float4*)s.redB)[k];
                S += (v4.x + v4.y) + (v4.z + v4.w);
            }
            w = wp / S;
            d = fmaf(w, dU, dM);
            q = fmaf(w * w, qU, fmaf(2.f * w, mm, q));
        }

        // ---- read-head addressing ----
        {
            float knr = sqrtf(s.red2[2] + s.red2[3] + s.red2[4]);
            float beta = s.sc[8], gg = s.sc[9];
            float sh0 = s.sc[10], sh1 = s.sc[11], sh2 = s.sc[12], gamma = s.sc[13];
            float p = __expf(beta * d / (sqrtf(q) * knr + EPSF));
            s.scratchU[tid] = p;
            s.scratchU[512 + tid] = w;
            float pw = p;
            #pragma unroll
            for (int o = 16; o; o >>= 1) pw += __shfl_xor_sync(0xffffffffu, pw, o);
            if (lane == 0) { s.redA[wid] = pw; st_peer(&s.redA[16 + wid], peer, pw); }
            if (tid == 511) { st_peer(&s.haloRp[0], peer, p); st_peer(&s.haloRv[0], peer, w); }
            if (tid == 0)   { st_peer(&s.haloRp[1], peer, p); st_peer(&s.haloRv[1], peer, w); }
            __syncthreads();
            CARRIVE();                                  // C4 arrive
            float pl = tid ? s.scratchU[tid - 1] : 0.f;
            float pr = (tid < 511) ? s.scratchU[tid + 1] : 0.f;
            float vl = tid ? s.scratchU[512 + tid - 1] : 0.f;
            float vr = (tid < 511) ? s.scratchU[512 + tid + 1] : 0.f;
            CWAIT();                                    // C4 wait
            if (tid == 0)   { pl = s.haloRp[0]; vl = s.haloRv[0]; }
            if (tid == 511) { pr = s.haloRp[1]; vr = s.haloRv[1]; }
            float Z = 0.f;
            #pragma unroll
            for (int k = 0; k < 8; ++k) {
                float4 v4 = ((const float4*)s.redA)[k];
                Z += (v4.x + v4.y) + (v4.z + v4.w);
            }
            float invZ = 1.f / Z;
            float ps = sh0 * pr + sh1 * p + sh2 * pl;
            float vs = sh0 * vr + sh1 * w + sh2 * vl;
            float ws = gg * invZ * ps + (1.f - gg) * vs;
            float wp = exp2f(gamma * __log2f(ws + EPSF));
            float sw = wp;
            #pragma unroll
            for (int o = 16; o; o >>= 1) sw += __shfl_xor_sync(0xffffffffu, sw, o);
            if (lane == 0) { s.redB[wid] = sw; st_peer(&s.redB[16 + wid], peer, sw); }
            CARRIVE();                                  // C5 arrive

            // hidden: deferred M update + unnormalized butterfly (scale by invS later)
            #pragma unroll
            for (int j4 = 0; j4 < 16; ++j4) {
                float4 ee = *(const float4*)(s.ev + 4 * j4);
                float4 aa = *(const float4*)(s.av + 4 * j4);
                #pragma unroll
                for (int e = 0; e < 4; ++e) {
                    int j = 4 * j4 + e;
                    float ev_ = (e==0)?ee.x:(e==1)?ee.y:(e==2)?ee.z:ee.w;
                    float av_ = (e==0)?aa.x:(e==1)?aa.y:(e==2)?aa.z:aa.w;
                    float mr = Mreg[j];
                    Mreg[j] = fmaf(w, fmaf(-mr, ev_, av_), mr);
                }
            }
            {
                float A[32];
                bool up = (lane & 16);
                #pragma unroll
                for (int i = 0; i < 32; ++i) {
                    float lo = wp * Mreg[i];
                    float hi = wp * Mreg[i + 32];
                    float keep = up ? hi : lo;
                    float send = up ? lo : hi;
                    A[i] = keep + __shfl_xor_sync(0xffffffffu, send, 16);
                }
                #pragma unroll
                for (int o = 8; o >= 1; o >>= 1) {
                    int hl2 = o << 1;
                    bool u2 = (lane & o);
                    #pragma unroll
                    for (int i = 0; i < 16; ++i) {
                        if (i < hl2) {
                            float keep = u2 ? A[i + hl2] : A[i];
                            float send = u2 ? A[i] : A[i + hl2];
                            A[i] = keep + __shfl_xor_sync(0xffffffffu, send, o);
                        }
                    }
                }
                s.scratchU[1024 + wid * 64 + 2 * lane]     = A[0];
                s.scratchU[1024 + wid * 64 + 2 * lane + 1] = A[1];
            }
            CWAIT();                                    // C5 wait (hidden)
            float S = 0.f;
            #pragma unroll
            for (int k = 0; k < 8; ++k) {
                float4 v4 = ((const float4*)s.redB)[k];
                S += (v4.x + v4.y) + (v4.z + v4.w);
            }
            float invS = 1.f / S;
            wr = wp * invS;                             // carried read weight
            __syncthreads();                            // order butterfly partials
            if (tid < 64) {
                float rl = 0.f;
                #pragma unroll
                for (int k = 0; k < 16; ++k) rl += s.scratchU[1024 + k * 64 + tid];
                rl *= invS;
                s.rv[tid] = rl;                         // local partial (completed below)
                st_peer(&s.rpart[tid], peer, rl);
            }
            CSYNC();                                    // C6
            if (tid < 64) s.rv[tid] += s.rpart[tid];
        }
        __syncthreads();                                // S9

        // ---- FC r-part ----
        if (tid < 64) {
            int gf = tid & 7, spf = tid >> 3;
            float4 acc = make_float4(0.f, 0.f, 0.f, 0.f);
            #pragma unroll
            for (int j = 0; j < 8; ++j) {
                float v = s.rv[spf * 8 + j];
                float4 w4 = Wf4[(size_t)(256 + spf * 8 + j) * 16 + rank * 8 + gf];
                acc.x = fmaf(v, w4.x, acc.x); acc.y = fmaf(v, w4.y, acc.y);
                acc.z = fmaf(v, w4.z, acc.z); acc.w = fmaf(v, w4.w, acc.w);
            }
            *(float4*)(s.scratchF + 512 + spf * 32 + 4 * gf) = acc;
        }
        __syncthreads();                                // S10
        if (tid < 32) {
            int o = rank * 32 + tid;
            float acc = s.bfs[o] + s.fcl[o] + s.fcp[par][o];
            #pragma unroll
            for (int k = 0; k < 8; ++k) acc += s.scratchF[512 + k * 32 + tid];
            out[((size_t)b * Tt + t) * 64 + o] = sigmoidf_(acc);
        }
    }
    CSYNC();
}

extern "C" void kernel_launch(void* const* d_in, const int* in_sizes, int n_in,
                              void* d_out, int out_size) {
    (void)in_sizes; (void)n_in; (void)out_size;
    cudaFuncSetAttribute(ntm_kernel, cudaFuncAttributeMaxDynamicSharedMemorySize,
                         (int)sizeof(Smem));
    ntm_kernel<<<128, NT, sizeof(Smem)>>>(
        (const float*)d_in[0],   // x
        (const float*)d_in[1],   // Wc
        (const float*)d_in[2],   // bc
        (const float*)d_in[3],   // Wr
        (const float*)d_in[4],   // br
        (const float*)d_in[5],   // Ww
        (const float*)d_in[6],   // bw
        (const float*)d_in[7],   // Wf
        (const float*)d_in[8],   // bf
        (const float*)d_in[9],   // r_bias
        (const float*)d_in[10],  // w_bias
        (const float*)d_in[11],  // M_bias
        (float*)d_out);
}

// round 9
// speedup vs baseline: 1.1048x; 1.1048x over previous
#include <cuda_runtime.h>
#include <cstdint>
#include <math.h>

#define Tt 64
#define NT 512
#define EPSF 1e-8f

__device__ __forceinline__ float sigmoidf_(float x) { return 1.f / (1.f + __expf(-x)); }
__device__ __forceinline__ float softplusf_(float x) { return (x > 20.f) ? x : log1pf(expf(x)); }

__device__ __forceinline__ uint32_t s2u(const void* p) {
    uint32_t a;
    asm("{ .reg .u64 t; cvta.to.shared.u64 t, %1; cvt.u32.u64 %0, t; }" : "=r"(a) : "l"(p));
    return a;
}
__device__ __forceinline__ void st_peer(const void* lp, uint32_t peer, float v) {
    uint32_t la = s2u(lp), ra;
    asm("mapa.shared::cluster.u32 %0, %1, %2;" : "=r"(ra) : "r"(la), "r"(peer));
    asm volatile("st.shared::cluster.f32 [%0], %1;" :: "r"(ra), "f"(v));
}
#define CSYNC() do { \
    asm volatile("barrier.cluster.arrive.aligned;" ::: "memory"); \
    asm volatile("barrier.cluster.wait.aligned;" ::: "memory"); } while (0)

struct __align__(16) Smem {
    float Whs[128 * 272];     // head weights: our K-half x all 272 outs
    float Wcs[64 * 128];      // controller r-part rows (cat K 64..127) x our 128 cols
    float xc[Tt * 128];       // precomputed x@Wc for our 128 cols, all steps
    float scratchU[2176];
    float scratchF[768];
    float chalf[128];
    float rv[64];
    float hl[272], hp[272];
    float fcl[64], fcp[2][64];
    float wtmp[512];
    float kw[64], kr[64], ev[64], av[64];
    float redA[32], redB[32];
    float red2[8], sc[16];
    float haloWp[2], haloWv[2], haloRp[2], haloRv[2];
    float rpart[64];
    float bws[200], brs[72], bfs[64], bcc[128];
};

__global__ __launch_bounds__(NT, 1) __cluster_dims__(2, 1, 1)
void ntm_kernel(const float* __restrict__ x,
                const float* __restrict__ Wc, const float* __restrict__ bc,
                const float* __restrict__ Wr, const float* __restrict__ br,
                const float* __restrict__ Ww, const float* __restrict__ bw,
                const float* __restrict__ Wf, const float* __restrict__ bf,
                const float* __restrict__ r_bias, const float* __restrict__ w_bias,
                const float* __restrict__ M_bias, float* __restrict__ out) {
    extern __shared__ float smem_raw[];
    Smem& s = *reinterpret_cast<Smem*>(smem_raw);
    const int tid = threadIdx.x;
    const int lane = tid & 31, wid = tid >> 5;
    uint32_t rank;
    asm("mov.u32 %0, %%cluster_ctarank;" : "=r"(rank));
    const uint32_t peer = rank ^ 1u;
    const int b = blockIdx.x >> 1;
    const float4* Wf4  = (const float4*)Wf;
    const float4* Wc4g = (const float4*)Wc;
    const float4* Wcs4 = (const float4*)s.Wcs;
    const float4* Whs4 = (const float4*)s.Whs;

    float Mreg[64];
    float q, d;

    // ---- init: weight slices ----
    for (int i = tid; i < 64 * 128; i += NT) {        // r-part rows of Wc
        int j = i >> 7, c = i & 127;
        s.Wcs[i] = Wc[(size_t)(64 + j) * 256 + rank * 128 + c];
    }
    for (int i = tid; i < 128 * 272; i += NT) {
        int j = i / 272, col = i - j * 272;
        int gk = rank * 128 + j;
        float v = 0.f;
        if (col < 198) v = Ww[(size_t)gk * 198 + col];
        else if (col < 268) v = Wr[(size_t)gk * 70 + (col - 198)];
        s.Whs[i] = v;
    }
    // ---- precompute xc[t][our 128 outs] = x_t @ Wc[0:64] ----
    for (int job = tid; job < Tt * 32; job += NT) {   // 2048 jobs, 4/thread
        int tt = job >> 5, g4 = job & 31;
        const float* xrow = x + ((size_t)b * Tt + tt) * 64;
        float4 acc = make_float4(0.f, 0.f, 0.f, 0.f);
        #pragma unroll 16
        for (int j = 0; j < 64; ++j) {
            float v = xrow[j];
            float4 w4 = Wc4g[(size_t)j * 64 + rank * 32 + g4];
            acc.x = fmaf(v, w4.x, acc.x); acc.y = fmaf(v, w4.y, acc.y);
            acc.z = fmaf(v, w4.z, acc.z); acc.w = fmaf(v, w4.w, acc.w);
        }
        *(float4*)(s.xc + tt * 128 + 4 * g4) = acc;
    }
    {
        const int row = rank * 512 + tid;
        q = 0.f;
        const float* Mb = M_bias + (size_t)row * 64;
        #pragma unroll
        for (int j = 0; j < 64; ++j) { float v = Mb[j]; Mreg[j] = v; q += v * v; }
    }
    float wr = w_bias[rank * 512 + tid];
    if (tid < 64)  s.rv[tid] = r_bias[tid];
    if (tid < 198) s.bws[tid] = bw[tid];
    if (tid < 70)  s.brs[tid] = br[tid];
    if (tid < 64)  s.bfs[tid] = bf[tid];
    if (tid < 128) s.bcc[tid] = bc[rank * 128 + tid];
    __syncthreads();
    CSYNC();

    for (int t = 0; t < Tt; ++t) {
        const int par = t & 1;
        // ---- loop-top: ctrl r-GEMV + FC r-part(step t-1) concurrently ----
        if (tid < 256) {
            int g = tid & 31, sp = tid >> 5;
            float4 acc = make_float4(0.f, 0.f, 0.f, 0.f);
            #pragma unroll
            for (int j = 0; j < 8; ++j) {
                float v = s.rv[sp * 8 + j];
                float4 w4 = Wcs4[(size_t)(sp * 8 + j) * 32 + g];
                acc.x = fmaf(v, w4.x, acc.x); acc.y = fmaf(v, w4.y, acc.y);
                acc.z = fmaf(v, w4.z, acc.z); acc.w = fmaf(v, w4.w, acc.w);
            }
            *(float4*)(s.scratchU + sp * 128 + 4 * g) = acc;
        } else if (tid < 320) {
            int ft = tid - 256, gf = ft & 7, spf = ft >> 3;
            float4 acc = make_float4(0.f, 0.f, 0.f, 0.f);
            #pragma unroll
            for (int j = 0; j < 8; ++j) {
                float v = s.rv[spf * 8 + j];
                float4 w4 = Wf4[(size_t)(256 + spf * 8 + j) * 16 + rank * 8 + gf];
                acc.x = fmaf(v, w4.x, acc.x); acc.y = fmaf(v, w4.y, acc.y);
                acc.z = fmaf(v, w4.z, acc.z); acc.w = fmaf(v, w4.w, acc.w);
            }
            *(float4*)(s.scratchF + 512 + spf * 32 + 4 * gf) = acc;
        }
        __syncthreads();                                // T1
        if (tid < 128) {
            float acc = s.xc[t * 128 + tid] + s.bcc[tid];
            #pragma unroll
            for (int k = 0; k < 8; ++k) acc += s.scratchU[k * 128 + tid];
            s.chalf[tid] = tanhf(acc);
        } else if (tid < 160 && t > 0) {
            int lo = tid - 128, o = rank * 32 + lo;
            float acc = s.bfs[o] + s.fcl[o] + s.fcp[par ^ 1][o];
            #pragma unroll
            for (int k = 0; k < 8; ++k) acc += s.scratchF[512 + k * 32 + lo];
            out[((size_t)b * Tt + (t - 1)) * 64 + o] = sigmoidf_(acc);
        }
        __syncthreads();                                // T2: chalf ready

        // ---- head GEMV partials + FC c-part ----
        {
            int g = tid % 68, sp = tid / 68;
            float4 acc = make_float4(0.f, 0.f, 0.f, 0.f);
            #pragma unroll
            for (int j = 0; j < 16; ++j) {
                float v = s.chalf[sp * 16 + j];
                float4 w4 = Whs4[(size_t)(sp * 16 + j) * 68 + g];
                acc.x = fmaf(v, w4.x, acc.x); acc.y = fmaf(v, w4.y, acc.y);
                acc.z = fmaf(v, w4.z, acc.z); acc.w = fmaf(v, w4.w, acc.w);
            }
            *(float4*)(s.scratchU + sp * 272 + 4 * g) = acc;
            if (tid < 32) {
                int g2 = 36 + tid;
                float4 a2 = make_float4(0.f, 0.f, 0.f, 0.f);
                #pragma unroll
                for (int j = 0; j < 16; ++j) {
                    float v = s.chalf[7 * 16 + j];
                    float4 w4 = Whs4[(size_t)(7 * 16 + j) * 68 + g2];
                    a2.x = fmaf(v, w4.x, a2.x); a2.y = fmaf(v, w4.y, a2.y);
                    a2.z = fmaf(v, w4.z, a2.z); a2.w = fmaf(v, w4.w, a2.w);
                }
                *(float4*)(s.scratchU + 7 * 272 + 4 * g2) = a2;
            }
            if (tid >= 384) {
                int ft = tid - 384, gf = ft & 15, spf = ft >> 4;
                float4 af = make_float4(0.f, 0.f, 0.f, 0.f);
                #pragma unroll
                for (int j = 0; j < 16; ++j) {
                    float v = s.chalf[spf * 16 + j];
                    float4 w4 = Wf4[(size_t)(rank * 128 + spf * 16 + j) * 16 + gf];
                    af.x = fmaf(v, w4.x, af.x); af.y = fmaf(v, w4.y, af.y);
                    af.z = fmaf(v, w4.z, af.z); af.w = fmaf(v, w4.w, af.w);
                }
                *(float4*)(s.scratchF + spf * 64 + 4 * gf) = af;
            }
        }
        __syncthreads();                                // S4
        if (tid < 272) {
            float acc = 0.f;
            #pragma unroll
            for (int k = 0; k < 8; ++k) acc += s.scratchU[k * 272 + tid];
            s.hl[tid] = acc;
            st_peer(&s.hp[tid], peer, acc);
        } else if (tid < 336) {
            int ft = tid - 272;
            float acc = 0.f;
            #pragma unroll
            for (int k = 0; k < 8; ++k) acc += s.scratchF[k * 64 + ft];
            s.fcl[ft] = acc;
            st_peer(&s.fcp[par][ft], peer, acc);
        }
        CSYNC();                                        // C1

        // ---- transforms ----
        {
            float hv = 0.f;
            if (tid < 268)
                hv = s.hl[tid] + s.hp[tid] + ((tid < 198) ? s.bws[tid] : s.brs[tid - 198]);
            float kv = 0.f;
            if (tid < 64 || (tid >= 198 && tid < 262)) kv = tanhf(hv);
            if (tid < 64) s.kw[tid] = kv;
            else if (tid < 70) {
                const unsigned m6 = 0x3Fu;
                float a0 = __shfl_sync(m6, hv, 2);
                float a1 = __shfl_sync(m6, hv, 3);
                float a2 = __shfl_sync(m6, hv, 4);
                if (lane == 0) s.sc[0] = softplusf_(hv);
                else if (lane == 1) s.sc[1] = sigmoidf_(hv);
                else if (lane == 5) s.sc[5] = 1.f + softplusf_(hv);
                else {
                    float m = fmaxf(a0, fmaxf(a1, a2));
                    float e0 = __expf(a0 - m), e1 = __expf(a1 - m), e2 = __expf(a2 - m);
                    float z = e0 + e1 + e2;
                    float mine = (lane == 2) ? e0 : (lane == 3) ? e1 : e2;
                    s.sc[2 + (lane - 2)] = mine / z;
                }
            }
            else if (tid < 134) s.ev[tid - 70] = sigmoidf_(hv);
            else if (tid < 198) s.av[tid - 134] = tanhf(hv);
            else if (tid < 262) s.kr[tid - 198] = kv;
            else if (tid < 268) {
                const unsigned m6 = 0xFC0u;
                float a0 = __shfl_sync(m6, hv, 8);
                float a1 = __shfl_sync(m6, hv, 9);
                float a2 = __shfl_sync(m6, hv, 10);
                if (lane == 6) s.sc[8] = softplusf_(hv);
                else if (lane == 7) s.sc[9] = sigmoidf_(hv);
                else if (lane == 11) s.sc[13] = 1.f + softplusf_(hv);
                else {
                    float m = fmaxf(a0, fmaxf(a1, a2));
                    float e0 = __expf(a0 - m), e1 = __expf(a1 - m), e2 = __expf(a2 - m);
                    float z = e0 + e1 + e2;
                    float mine = (lane == 8) ? e0 : (lane == 9) ? e1 : e2;
                    s.sc[10 + (lane - 8)] = mine / z;
                }
            }
            float qq = kv * kv;
            if (wid < 2 || (wid >= 6 && wid <= 8)) {
                #pragma unroll
                for (int o = 16; o; o >>= 1) qq += __shfl_xor_sync(0xffffffffu, qq, o);
                if (lane == 0) s.red2[wid < 2 ? wid : wid - 4] = qq;
            }
        }
        __syncthreads();                                // S5

        // ---- Pass A ----
        d = 0.f;
        #pragma unroll
        for (int j4 = 0; j4 < 16; ++j4) {
            float4 kk = *(const float4*)(s.kw + 4 * j4);
            d += Mreg[4*j4]*kk.x + Mreg[4*j4+1]*kk.y + Mreg[4*j4+2]*kk.z + Mreg[4*j4+3]*kk.w;
        }

        // ---- write-head addressing (R7 style) ----
        float w;
        {
            float knw = sqrtf(s.red2[0] + s.red2[1]);
            float beta = s.sc[0], gg = s.sc[1];
            float sh0 = s.sc[2], sh1 = s.sc[3], sh2 = s.sc[4], gamma = s.sc[5];
            float p = __expf(beta * d / (sqrtf(q) * knw + EPSF));
            float pw = p;
            #pragma unroll
            for (int o = 16; o; o >>= 1) pw += __shfl_xor_sync(0xffffffffu, pw, o);
            if (lane == 0) { s.redA[wid] = pw; st_peer(&s.redA[16 + wid], peer, pw); }
            if (tid == 511) { st_peer(&s.haloWp[0], peer, p); st_peer(&s.haloWv[0], peer, wr); }
            if (tid == 0)   { st_peer(&s.haloWp[1], peer, p); st_peer(&s.haloWv[1], peer, wr); }
            CSYNC();                                    // C2
            float Z = 0.f;
            #pragma unroll
            for (int k = 0; k < 8; ++k) {
                float4 v4 = ((const float4*)s.redA)[k];
                Z += (v4.x + v4.y) + (v4.z + v4.w);
            }
            float invZ = 1.f / Z;
            float wg = gg * p * invZ + (1.f - gg) * wr;
            s.wtmp[tid] = wg;
            __syncthreads();                            // S6
            float h0 = gg * s.haloWp[0] * invZ + (1.f - gg) * s.haloWv[0];
            float h1 = gg * s.haloWp[1] * invZ + (1.f - gg) * s.haloWv[1];
            float left  = tid ? s.wtmp[tid - 1] : h0;
            float right = (tid < 511) ? s.wtmp[tid + 1] : h1;
            float ws = sh0 * right + sh1 * wg + sh2 * left;
            float wp = exp2f(gamma * __log2f(ws + EPSF));
            float sw = wp;
            #pragma unroll
            for (int o = 16; o; o >>= 1) sw += __shfl_xor_sync(0xffffffffu, sw, o);
            if (lane == 0) { s.redB[wid] = sw; st_peer(&s.redB[16 + wid], peer, sw); }
            CSYNC();                                    // C3
            float S = 0.f;
            #pragma unroll
            for (int k = 0; k < 8; ++k) {
                float4 v4 = ((const float4*)s.redB)[k];
                S += (v4.x + v4.y) + (v4.z + v4.w);
            }
            w = wp / S;
        }

        // ---- Pass B: erase/add + dot(M',kr) + sumsq ----
        {
            float nd = 0.f, nq = 0.f;
            #pragma unroll
            for (int j4 = 0; j4 < 16; ++j4) {
                float4 kk = *(const float4*)(s.kr + 4 * j4);
                float4 ee = *(const float4*)(s.ev + 4 * j4);
                float4 aa = *(const float4*)(s.av + 4 * j4);
                #pragma unroll
                for (int e = 0; e < 4; ++e) {
                    int j = 4 * j4 + e;
                    float ev_ = (e==0)?ee.x:(e==1)?ee.y:(e==2)?ee.z:ee.w;
                    float av_ = (e==0)?aa.x:(e==1)?aa.y:(e==2)?aa.z:aa.w;
                    float kv_ = (e==0)?kk.x:(e==1)?kk.y:(e==2)?kk.z:kk.w;
                    float mr = Mreg[j];
                    mr = mr * (1.f - w * ev_) + w * av_;
                    Mreg[j] = mr;
                    nd = fmaf(mr, kv_, nd); nq = fmaf(mr, mr, nq);
                }
            }
            d = nd; q = nq;
        }

        // ---- read-head addressing + merged C5/C6 ----
        {
            float knr = sqrtf(s.red2[2] + s.red2[3] + s.red2[4]);
            float beta = s.sc[8], gg = s.sc[9];
            float sh0 = s.sc[10], sh1 = s.sc[11], sh2 = s.sc[12], gamma = s.sc[13];
            float p = __expf(beta * d / (sqrtf(q) * knr + EPSF));
            float pw = p;
            #pragma unroll
            for (int o = 16; o; o >>= 1) pw += __shfl_xor_sync(0xffffffffu, pw, o);
            if (lane == 0) { s.redA[wid] = pw; st_peer(&s.redA[16 + wid], peer, pw); }
            if (tid == 511) { st_peer(&s.haloRp[0], peer, p); st_peer(&s.haloRv[0], peer, w); }
            if (tid == 0)   { st_peer(&s.haloRp[1], peer, p); st_peer(&s.haloRv[1], peer, w); }
            CSYNC();                                    // C4
            float Z = 0.f;
            #pragma unroll
            for (int k = 0; k < 8; ++k) {
                float4 v4 = ((const float4*)s.redA)[k];
                Z += (v4.x + v4.y) + (v4.z + v4.w);
            }
            float invZ = 1.f / Z;
            float wg = gg * p * invZ + (1.f - gg) * w;
            s.wtmp[tid] = wg;
            __syncthreads();                            // S7
            float h0 = gg * s.haloRp[0] * invZ + (1.f - gg) * s.haloRv[0];
            float h1 = gg * s.haloRp[1] * invZ + (1.f - gg) * s.haloRv[1];
            float left  = tid ? s.wtmp[tid - 1] : h0;
            float right = (tid < 511) ? s.wtmp[tid + 1] : h1;
            float ws = sh0 * right + sh1 * wg + sh2 * left;
            float wp = exp2f(gamma * __log2f(ws + EPSF));
            float sw = wp;
            #pragma unroll
            for (int o = 16; o; o >>= 1) sw += __shfl_xor_sync(0xffffffffu, sw, o);
            if (lane == 0) { s.redB[wid] = sw; st_peer(&s.redB[16 + wid], peer, sw); }

            // unnormalized butterfly with wp (before the S barrier)
            {
                float A[32];
                bool up = (lane & 16);
                #pragma unroll
                for (int i = 0; i < 32; ++i) {
                    float lo = wp * Mreg[i];
                    float hi = wp * Mreg[i + 32];
                    float keep = up ? hi : lo;
                    float send = up ? lo : hi;
                    A[i] = keep + __shfl_xor_sync(0xffffffffu, send, 16);
                }
                #pragma unroll
                for (int o = 8; o >= 1; o >>= 1) {
                    int hl2 = o << 1;
                    bool u2 = (lane & o);
                    #pragma unroll
                    for (int i = 0; i < 16; ++i) {
                        if (i < hl2) {
                            float keep = u2 ? A[i + hl2] : A[i];
                            float send = u2 ? A[i] : A[i + hl2];
                            A[i] = keep + __shfl_xor_sync(0xffffffffu, send, o);
                        }
                    }
                }
                s.scratchU[1024 + wid * 64 + 2 * lane]     = A[0];
                s.scratchU[1024 + wid * 64 + 2 * lane + 1] = A[1];
            }
            __syncthreads();                            // S8
            float rlu = 0.f;
            if (tid < 64) {
                #pragma unroll
                for (int k = 0; k < 16; ++k) rlu += s.scratchU[1024 + k * 64 + tid];
                st_peer(&s.rpart[tid], peer, rlu);
            }
            CSYNC();                                    // C5 merged (S partials + r partials)
            float S = 0.f;
            #pragma unroll
            for (int k = 0; k < 8; ++k) {
                float4 v4 = ((const float4*)s.redB)[k];
                S += (v4.x + v4.y) + (v4.z + v4.w);
            }
            float invS = 1.f / S;
            wr = wp * invS;
            if (tid < 64) s.rv[tid] = (rlu + s.rpart[tid]) * invS;
        }
        __syncthreads();                                // S9: rv ready for next loop-top
    }

    // ---- epilogue: output for t = 63 ----
    if (tid < 64) {
        int gf = tid & 7, spf = tid >> 3;
        float4 acc = make_float4(0.f, 0.f, 0.f, 0.f);
        #pragma unroll
        for (int j = 0; j < 8; ++j) {
            float v = s.rv[spf * 8 + j];
            float4 w4 = Wf4[(size_t)(256 + spf * 8 + j) * 16 + rank * 8 + gf];
            acc.x = fmaf(v, w4.x, acc.x); acc.y = fmaf(v, w4.y, acc.y);
            acc.z = fmaf(v, w4.z, acc.z); acc.w = fmaf(v, w4.w, acc.w);
        }
        *(float4*)(s.scratchF + 512 + spf * 32 + 4 * gf) = acc;
    }
    __syncthreads();
    if (tid < 32) {
        int o = rank * 32 + tid;
        float acc = s.bfs[o] + s.fcl[o] + s.fcp[1][o];
        #pragma unroll
        for (int k = 0; k < 8; ++k) acc += s.scratchF[512 + k * 32 + tid];
        out[((size_t)b * Tt + 63) * 64 + o] = sigmoidf_(acc);
    }
    CSYNC();
}

extern "C" void kernel_launch(void* const* d_in, const int* in_sizes, int n_in,
                              void* d_out, int out_size) {
    (void)in_sizes; (void)n_in; (void)out_size;
    cudaFuncSetAttribute(ntm_kernel, cudaFuncAttributeMaxDynamicSharedMemorySize,
                         (int)sizeof(Smem));
    ntm_kernel<<<128, NT, sizeof(Smem)>>>(
        (const float*)d_in[0],   // x
        (const float*)d_in[1],   // Wc
        (const float*)d_in[2],   // bc
        (const float*)d_in[3],   // Wr
        (const float*)d_in[4],   // br
        (const float*)d_in[5],   // Ww
        (const float*)d_in[6],   // bw
        (const float*)d_in[7],   // Wf
        (const float*)d_in[8],   // bf
        (const float*)d_in[9],   // r_bias
        (const float*)d_in[10],  // w_bias
        (const float*)d_in[11],  // M_bias
        (float*)d_out);
}

// round 11
// speedup vs baseline: 1.1642x; 1.0538x over previous
#include <cuda_runtime.h>
#include <cstdint>
#include <math.h>

#define Tt 64
#define NT 512
#define EPSF 1e-8f

__device__ __forceinline__ float sigmoidf_(float x) { return __fdividef(1.f, 1.f + __expf(-x)); }
__device__ __forceinline__ float softplusf_(float x) { return (x > 20.f) ? x : log1pf(expf(x)); }
__device__ __forceinline__ float ftanh(float x) {
    float e = __expf(fminf(fmaxf(2.f * x, -30.f), 30.f));
    return __fdividef(e - 1.f, e + 1.f);
}

__device__ __forceinline__ uint32_t s2u(const void* p) {
    uint32_t a;
    asm("{ .reg .u64 t; cvta.to.shared.u64 t, %1; cvt.u32.u64 %0, t; }" : "=r"(a) : "l"(p));
    return a;
}
__device__ __forceinline__ void st_peer(const void* lp, uint32_t peer, float v) {
    uint32_t la = s2u(lp), ra;
    asm("mapa.shared::cluster.u32 %0, %1, %2;" : "=r"(ra) : "r"(la), "r"(peer));
    asm volatile("st.shared::cluster.f32 [%0], %1;" :: "r"(ra), "f"(v));
}
#define CSYNC() do { \
    asm volatile("barrier.cluster.arrive.aligned;" ::: "memory"); \
    asm volatile("barrier.cluster.wait.aligned;" ::: "memory"); } while (0)

struct __align__(16) Smem {
    float Whs[128 * 272];     // head weights: our K-half x all 272 outs
    float Wcs[64 * 128];      // controller r-part rows x our 128 cols
    float xc[Tt * 128];       // precomputed x@Wc for our 128 cols
    float scratchU[2448];     // 9 rows x 272: head partials / pArr,vArr / butterfly
    float scratchF[1280];     // FC c-part 16x64 | r-part 8x32 @1024
    float chalf[128];
    float rv[64];
    float hl[272], hp[272];
    float fcl[64], fcp[2][64];
    float kw[64], kr[64], ev[64], av[64];
    float redA[32], redB[32];
    float red2[8], sc[16];
    float haloWp[2], haloWv[2], haloRp[2], haloRv[2];
    float rpart[64];
    float bws[200], brs[72], bfs[64], bcc[128];
};

__global__ __launch_bounds__(NT, 1) __cluster_dims__(2, 1, 1)
void ntm_kernel(const float* __restrict__ x,
                const float* __restrict__ Wc, const float* __restrict__ bc,
                const float* __restrict__ Wr, const float* __restrict__ br,
                const float* __restrict__ Ww, const float* __restrict__ bw,
                const float* __restrict__ Wf, const float* __restrict__ bf,
                const float* __restrict__ r_bias, const float* __restrict__ w_bias,
                const float* __restrict__ M_bias, float* __restrict__ out) {
    extern __shared__ float smem_raw[];
    Smem& s = *reinterpret_cast<Smem*>(smem_raw);
    const int tid = threadIdx.x;
    const int lane = tid & 31, wid = tid >> 5;
    uint32_t rank;
    asm("mov.u32 %0, %%cluster_ctarank;" : "=r"(rank));
    const uint32_t peer = rank ^ 1u;
    const int b = blockIdx.x >> 1;
    const float4* Wf4  = (const float4*)Wf;
    const float4* Wc4g = (const float4*)Wc;
    const float4* Wcs4 = (const float4*)s.Wcs;
    const float4* Whs4 = (const float4*)s.Whs;

    float Mreg[64];
    float q, d;

    // ---- init ----
    for (int i = tid; i < 64 * 128; i += NT) {
        int j = i >> 7, c = i & 127;
        s.Wcs[i] = Wc[(size_t)(64 + j) * 256 + rank * 128 + c];
    }
    for (int i = tid; i < 128 * 272; i += NT) {
        int j = i / 272, col = i - j * 272;
        int gk = rank * 128 + j;
        float v = 0.f;
        if (col < 198) v = Ww[(size_t)gk * 198 + col];
        else if (col < 268) v = Wr[(size_t)gk * 70 + (col - 198)];
        s.Whs[i] = v;
    }
    for (int job = tid; job < Tt * 32; job += NT) {
        int tt = job >> 5, g4 = job & 31;
        const float* xrow = x + ((size_t)b * Tt + tt) * 64;
        float4 acc = make_float4(0.f, 0.f, 0.f, 0.f);
        #pragma unroll 16
        for (int j = 0; j < 64; ++j) {
            float v = xrow[j];
            float4 w4 = Wc4g[(size_t)j * 64 + rank * 32 + g4];
            acc.x = fmaf(v, w4.x, acc.x); acc.y = fmaf(v, w4.y, acc.y);
            acc.z = fmaf(v, w4.z, acc.z); acc.w = fmaf(v, w4.w, acc.w);
        }
        *(float4*)(s.xc + tt * 128 + 4 * g4) = acc;
    }
    {
        const int row = rank * 512 + tid;
        q = 0.f;
        const float* Mb = M_bias + (size_t)row * 64;
        #pragma unroll
        for (int j = 0; j < 64; ++j) { float v = Mb[j]; Mreg[j] = v; q += v * v; }
    }
    float wr = w_bias[rank * 512 + tid];
    if (tid < 64)  s.rv[tid] = r_bias[tid];
    if (tid < 198) s.bws[tid] = bw[tid];
    if (tid < 70)  s.brs[tid] = br[tid];
    if (tid < 64)  s.bfs[tid] = bf[tid];
    if (tid < 128) s.bcc[tid] = bc[rank * 128 + tid];
    __syncthreads();
    CSYNC();

    for (int t = 0; t < Tt; ++t) {
        const int par = t & 1;
        // ---- loop-top: ctrl r-GEMV + FC r-part(step t-1) ----
        if (tid < 256) {
            int g = tid & 31, sp = tid >> 5;
            float4 acc = make_float4(0.f, 0.f, 0.f, 0.f);
            #pragma unroll
            for (int j = 0; j < 8; ++j) {
                float v = s.rv[sp * 8 + j];
                float4 w4 = Wcs4[(size_t)(sp * 8 + j) * 32 + g];
                acc.x = fmaf(v, w4.x, acc.x); acc.y = fmaf(v, w4.y, acc.y);
                acc.z = fmaf(v, w4.z, acc.z); acc.w = fmaf(v, w4.w, acc.w);
            }
            *(float4*)(s.scratchU + sp * 128 + 4 * g) = acc;
        } else if (tid < 320) {
            int ft = tid - 256, gf = ft & 7, spf = ft >> 3;
            float4 acc = make_float4(0.f, 0.f, 0.f, 0.f);
            #pragma unroll
            for (int j = 0; j < 8; ++j) {
                float v = s.rv[spf * 8 + j];
                float4 w4 = Wf4[(size_t)(256 + spf * 8 + j) * 16 + rank * 8 + gf];
                acc.x = fmaf(v, w4.x, acc.x); acc.y = fmaf(v, w4.y, acc.y);
                acc.z = fmaf(v, w4.z, acc.z); acc.w = fmaf(v, w4.w, acc.w);
            }
            *(float4*)(s.scratchF + 1024 + spf * 32 + 4 * gf) = acc;
        }
        __syncthreads();                                // T1
        if (tid < 128) {
            float acc = s.xc[t * 128 + tid] + s.bcc[tid];
            #pragma unroll
            for (int k = 0; k < 8; ++k) acc += s.scratchU[k * 128 + tid];
            s.chalf[tid] = ftanh(acc);
        } else if (tid < 160 && t > 0) {
            int lo = tid - 128, o = rank * 32 + lo;
            float acc = s.bfs[o] + s.fcl[o] + s.fcp[par ^ 1][o];
            #pragma unroll
            for (int k = 0; k < 8; ++k) acc += s.scratchF[1024 + k * 32 + lo];
            out[((size_t)b * Tt + (t - 1)) * 64 + o] = sigmoidf_(acc);
        }
        __syncthreads();                                // T2

        // ---- head GEMV partials (balanced) + FC c-part ----
        {
            int g = tid % 68, sp = tid / 68;
            float4 acc = make_float4(0.f, 0.f, 0.f, 0.f);
            #pragma unroll
            for (int j = 0; j < 16; ++j) {
                float v = s.chalf[sp * 16 + j];
                float4 w4 = Whs4[(size_t)(sp * 16 + j) * 68 + g];
                acc.x = fmaf(v, w4.x, acc.x); acc.y = fmaf(v, w4.y, acc.y);
                acc.z = fmaf(v, w4.z, acc.z); acc.w = fmaf(v, w4.w, acc.w);
            }
            *(float4*)(s.scratchU + sp * 272 + 4 * g) = acc;
            if (tid < 64) {                             // missing (sp=7, g=36..67) as 8-iter halves
                int g2 = 36 + (tid >> 1), h = tid & 1;
                float4 a2 = make_float4(0.f, 0.f, 0.f, 0.f);
                #pragma unroll
                for (int j = 0; j < 8; ++j) {
                    int c = 112 + h * 8 + j;
                    float v = s.chalf[c];
                    float4 w4 = Whs4[(size_t)c * 68 + g2];
                    a2.x = fmaf(v, w4.x, a2.x); a2.y = fmaf(v, w4.y, a2.y);
                    a2.z = fmaf(v, w4.z, a2.z); a2.w = fmaf(v, w4.w, a2.w);
                }
                *(float4*)(s.scratchU + (7 + h) * 272 + 4 * g2) = a2;
            } else if (tid < 320) {                     // FC c-part: 16 grp x 16 sp(8K)
                int ft = tid - 64, gf = ft & 15, spf = ft >> 4;
                float4 af = make_float4(0.f, 0.f, 0.f, 0.f);
                #pragma unroll
                for (int j = 0; j < 8; ++j) {
                    float v = s.chalf[spf * 8 + j];
                    float4 w4 = Wf4[(size_t)(rank * 128 + spf * 8 + j) * 16 + gf];
                    af.x = fmaf(v, w4.x, af.x); af.y = fmaf(v, w4.y, af.y);
                    af.z = fmaf(v, w4.z, af.z); af.w = fmaf(v, w4.w, af.w);
                }
                *(float4*)(s.scratchF + spf * 64 + 4 * gf) = af;
            }
        }
        __syncthreads();                                // S4
        if (tid < 272) {
            float acc = 0.f;
            #pragma unroll
            for (int k = 0; k < 8; ++k) acc += s.scratchU[k * 272 + tid];
            if (tid >= 144) acc += s.scratchU[8 * 272 + tid];
            s.hl[tid] = acc;
            st_peer(&s.hp[tid], peer, acc);
        } else if (tid < 336) {
            int ft = tid - 272;
            float acc = 0.f;
            #pragma unroll
            for (int k = 0; k < 16; ++k) acc += s.scratchF[k * 64 + ft];
            s.fcl[ft] = acc;
            st_peer(&s.fcp[par][ft], peer, acc);
        }
        CSYNC();                                        // C1

        // ---- transforms ----
        {
            float hv = 0.f;
            if (tid < 268)
                hv = s.hl[tid] + s.hp[tid] + ((tid < 198) ? s.bws[tid] : s.brs[tid - 198]);
            float kv = 0.f;
            if (tid < 64 || (tid >= 198 && tid < 262)) kv = ftanh(hv);
            if (tid < 64) s.kw[tid] = kv;
            else if (tid < 70) {
                const unsigned m6 = 0x3Fu;
                float a0 = __shfl_sync(m6, hv, 2);
                float a1 = __shfl_sync(m6, hv, 3);
                float a2 = __shfl_sync(m6, hv, 4);
                if (lane == 0) s.sc[0] = softplusf_(hv);
                else if (lane == 1) s.sc[1] = sigmoidf_(hv);
                else if (lane == 5) s.sc[5] = 1.f + softplusf_(hv);
                else {
                    float m = fmaxf(a0, fmaxf(a1, a2));
                    float e0 = __expf(a0 - m), e1 = __expf(a1 - m), e2 = __expf(a2 - m);
                    float z = e0 + e1 + e2;
                    float mine = (lane == 2) ? e0 : (lane == 3) ? e1 : e2;
                    s.sc[2 + (lane - 2)] = __fdividef(mine, z);
                }
            }
            else if (tid < 134) s.ev[tid - 70] = sigmoidf_(hv);
            else if (tid < 198) s.av[tid - 134] = ftanh(hv);
            else if (tid < 262) s.kr[tid - 198] = kv;
            else if (tid < 268) {
                const unsigned m6 = 0xFC0u;
                float a0 = __shfl_sync(m6, hv, 8);
                float a1 = __shfl_sync(m6, hv, 9);
                float a2 = __shfl_sync(m6, hv, 10);
                if (lane == 6) s.sc[8] = softplusf_(hv);
                else if (lane == 7) s.sc[9] = sigmoidf_(hv);
                else if (lane == 11) s.sc[13] = 1.f + softplusf_(hv);
                else {
                    float m = fmaxf(a0, fmaxf(a1, a2));
                    float e0 = __expf(a0 - m), e1 = __expf(a1 - m), e2 = __expf(a2 - m);
                    float z = e0 + e1 + e2;
                    float mine = (lane == 8) ? e0 : (lane == 9) ? e1 : e2;
                    s.sc[10 + (lane - 8)] = __fdividef(mine, z);
                }
            }
            float qq = kv * kv;
            if (wid < 2 || (wid >= 6 && wid <= 8)) {
                #pragma unroll
                for (int o = 16; o; o >>= 1) qq += __shfl_xor_sync(0xffffffffu, qq, o);
                if (lane == 0) s.red2[wid < 2 ? wid : wid - 4] = qq;
            }
        }
        __syncthreads();                                // S5

        // ---- Pass A ----
        d = 0.f;
        #pragma unroll
        for (int j4 = 0; j4 < 16; ++j4) {
            float4 kk = *(const float4*)(s.kw + 4 * j4);
            d += Mreg[4*j4]*kk.x + Mreg[4*j4+1]*kk.y + Mreg[4*j4+2]*kk.z + Mreg[4*j4+3]*kk.w;
        }

        // ---- write-head addressing (raw-shift decomposition; no extra syncs) ----
        float w;
        {
            float knw = __fsqrt_rn(s.red2[0] + s.red2[1]);
            float beta = s.sc[0], gg = s.sc[1];
            float sh0 = s.sc[2], sh1 = s.sc[3], sh2 = s.sc[4], gamma = s.sc[5];
            float p = __expf(__fdividef(beta * d, __fsqrt_rn(q) * knw + EPSF));
            s.scratchU[tid] = p;
            s.scratchU[512 + tid] = wr;
            float pw = p;
            #pragma unroll
            for (int o = 16; o; o >>= 1) pw += __shfl_xor_sync(0xffffffffu, pw, o);
            if (lane == 0) { s.redA[wid] = pw; st_peer(&s.redA[16 + wid], peer, pw); }
            if (tid == 511) { st_peer(&s.haloWp[0], peer, p); st_peer(&s.haloWv[0], peer, wr); }
            if (tid == 0)   { st_peer(&s.haloWp[1], peer, p); st_peer(&s.haloWv[1], peer, wr); }
            CSYNC();                                    // C2 (block-wide: orders local smem too)
            float Z = 0.f;
            #pragma unroll
            for (int k = 0; k < 8; ++k) {
                float4 v4 = ((const float4*)s.redA)[k];
                Z += (v4.x + v4.y) + (v4.z + v4.w);
            }
            float invZ = __fdividef(1.f, Z);
            float pl = tid ? s.scratchU[tid - 1] : s.haloWp[0];
            float pr = (tid < 511) ? s.scratchU[tid + 1] : s.haloWp[1];
            float vl = tid ? s.scratchU[512 + tid - 1] : s.haloWv[0];
            float vr = (tid < 511) ? s.scratchU[512 + tid + 1] : s.haloWv[1];
            float ps = sh0 * pr + sh1 * p  + sh2 * pl;
            float vs = sh0 * vr + sh1 * wr + sh2 * vl;
            float ws = gg * invZ * ps + (1.f - gg) * vs;
            float wp = exp2f(gamma * __log2f(ws + EPSF));
            float sw = wp;
            #pragma unroll
            for (int o = 16; o; o >>= 1) sw += __shfl_xor_sync(0xffffffffu, sw, o);
            if (lane == 0) { s.redB[wid] = sw; st_peer(&s.redB[16 + wid], peer, sw); }
            CSYNC();                                    // C3
            float S = 0.f;
            #pragma unroll
            for (int k = 0; k < 8; ++k) {
                float4 v4 = ((const float4*)s.redB)[k];
                S += (v4.x + v4.y) + (v4.z + v4.w);
            }
            w = wp * __fdividef(1.f, S);
        }

        // ---- Pass B ----
        {
            float nd = 0.f, nq = 0.f;
            #pragma unroll
            for (int j4 = 0; j4 < 16; ++j4) {
                float4 kk = *(const float4*)(s.kr + 4 * j4);
                float4 ee = *(const float4*)(s.ev + 4 * j4);
                float4 aa = *(const float4*)(s.av + 4 * j4);
                #pragma unroll
                for (int e = 0; e < 4; ++e) {
                    int j = 4 * j4 + e;
                    float ev_ = (e==0)?ee.x:(e==1)?ee.y:(e==2)?ee.z:ee.w;
                    float av_ = (e==0)?aa.x:(e==1)?aa.y:(e==2)?aa.z:aa.w;
                    float kv_ = (e==0)?kk.x:(e==1)?kk.y:(e==2)?kk.z:kk.w;
                    float mr = Mreg[j];
                    mr = mr * (1.f - w * ev_) + w * av_;
                    Mreg[j] = mr;
                    nd = fmaf(mr, kv_, nd); nq = fmaf(mr, mr, nq);
                }
            }
            d = nd; q = nq;
        }

        // ---- read-head addressing + merged C5 ----
        {
            float knr = __fsqrt_rn(s.red2[2] + s.red2[3] + s.red2[4]);
            float beta = s.sc[8], gg = s.sc[9];
            float sh0 = s.sc[10], sh1 = s.sc[11], sh2 = s.sc[12], gamma = s.sc[13];
            float p = __expf(__fdividef(beta * d, __fsqrt_rn(q) * knr + EPSF));
            s.scratchU[tid] = p;
            s.scratchU[512 + tid] = w;
            float pw = p;
            #pragma unroll
            for (int o = 16; o; o >>= 1) pw += __shfl_xor_sync(0xffffffffu, pw, o);
            if (lane == 0) { s.redA[wid] = pw; st_peer(&s.redA[16 + wid], peer, pw); }
            if (tid == 511) { st_peer(&s.haloRp[0], peer, p); st_peer(&s.haloRv[0], peer, w); }
            if (tid == 0)   { st_peer(&s.haloRp[1], peer, p); st_peer(&s.haloRv[1], peer, w); }
            CSYNC();                                    // C4
            float Z = 0.f;
            #pragma unroll
            for (int k = 0; k < 8; ++k) {
                float4 v4 = ((const float4*)s.redA)[k];
                Z += (v4.x + v4.y) + (v4.z + v4.w);
            }
            float invZ = __fdividef(1.f, Z);
            float pl = tid ? s.scratchU[tid - 1] : s.haloRp[0];
            float pr = (tid < 511) ? s.scratchU[tid + 1] : s.haloRp[1];
            float vl = tid ? s.scratchU[512 + tid - 1] : s.haloRv[0];
            float vr = (tid < 511) ? s.scratchU[512 + tid + 1] : s.haloRv[1];
            float ps = sh0 * pr + sh1 * p + sh2 * pl;
            float vs = sh0 * vr + sh1 * w + sh2 * vl;
            float ws = gg * invZ * ps + (1.f - gg) * vs;
            float wp = exp2f(gamma * __log2f(ws + EPSF));
            float sw = wp;
            #pragma unroll
            for (int o = 16; o; o >>= 1) sw += __shfl_xor_sync(0xffffffffu, sw, o);
            if (lane == 0) { s.redB[wid] = sw; st_peer(&s.redB[16 + wid], peer, sw); }

            // unnormalized butterfly with wp
            {
                float A[32];
                bool up = (lane & 16);
                #pragma unroll
                for (int i = 0; i < 32; ++i) {
                    float lo = wp * Mreg[i];
                    float hi = wp * Mreg[i + 32];
                    float keep = up ? hi : lo;
                    float send = up ? lo : hi;
                    A[i] = keep + __shfl_xor_sync(0xffffffffu, send, 16);
                }
                #pragma unroll
                for (int o = 8; o >= 1; o >>= 1) {
                    int hl2 = o << 1;
                    bool u2 = (lane & o);
                    #pragma unroll
                    for (int i = 0; i < 16; ++i) {
                        if (i < hl2) {
                            float keep = u2 ? A[i + hl2] : A[i];
                            float send = u2 ? A[i] : A[i + hl2];
                            A[i] = keep + __shfl_xor_sync(0xffffffffu, send, o);
                        }
                    }
                }
                s.scratchU[1024 + wid * 64 + 2 * lane]     = A[0];
                s.scratchU[1024 + wid * 64 + 2 * lane + 1] = A[1];
            }
            __syncthreads();                            // S8
            float rlu = 0.f;
            if (tid < 64) {
                #pragma unroll
                for (int k = 0; k < 16; ++k) rlu += s.scratchU[1024 + k * 64 + tid];
                st_peer(&s.rpart[tid], peer, rlu);
            }
            CSYNC();                                    // C5 (S partials + r partials)
            float S = 0.f;
            #pragma unroll
            for (int k = 0; k < 8; ++k) {
                float4 v4 = ((const float4*)s.redB)[k];
                S += (v4.x + v4.y) + (v4.z + v4.w);
            }
            float invS = __fdividef(1.f, S);
            wr = wp * invS;
            if (tid < 64) s.rv[tid] = (rlu + s.rpart[tid]) * invS;
        }
        __syncthreads();                                // S9
    }

    // ---- epilogue: output t = 63 ----
    if (tid < 64) {
        int gf = tid & 7, spf = tid >> 3;
        float4 acc = make_float4(0.f, 0.f, 0.f, 0.f);
        #pragma unroll
        for (int j = 0; j < 8; ++j) {
            float v = s.rv[spf * 8 + j];
            float4 w4 = Wf4[(size_t)(256 + spf * 8 + j) * 16 + rank * 8 + gf];
            acc.x = fmaf(v, w4.x, acc.x); acc.y = fmaf(v, w4.y, acc.y);
            acc.z = fmaf(v, w4.z, acc.z); acc.w = fmaf(v, w4.w, acc.w);
        }
        *(float4*)(s.scratchF + 1024 + spf * 32 + 4 * gf) = acc;
    }
    __syncthreads();
    if (tid < 32) {
        int o = rank * 32 + tid;
        float acc = s.bfs[o] + s.fcl[o] + s.fcp[1][o];
        #pragma unroll
        for (int k = 0; k < 8; ++k) acc += s.scratchF[1024 + k * 32 + tid];
        out[((size_t)b * Tt + 63) * 64 + o] = sigmoidf_(acc);
    }
    CSYNC();
}

extern "C" void kernel_launch(void* const* d_in, const int* in_sizes, int n_in,
                              void* d_out, int out_size) {
    (void)in_sizes; (void)n_in; (void)out_size;
    cudaFuncSetAttribute(ntm_kernel, cudaFuncAttributeMaxDynamicSharedMemorySize,
                         (int)sizeof(Smem));
    ntm_kernel<<<128, NT, sizeof(Smem)>>>(
        (const float*)d_in[0],   // x
        (const float*)d_in[1],   // Wc
        (const float*)d_in[2],   // bc
        (const float*)d_in[3],   // Wr
        (const float*)d_in[4],   // br
        (const float*)d_in[5],   // Ww
        (const float*)d_in[6],   // bw
        (const float*)d_in[7],   // Wf
        (const float*)d_in[8],   // bf
        (const float*)d_in[9],   // r_bias
        (const float*)d_in[10],  // w_bias
        (const float*)d_in[11],  // M_bias
        (float*)d_out);
}